// round 1
// baseline (speedup 1.0000x reference)
#include <cuda_runtime.h>
#include <math.h>

#define BATCH 2
#define SEQ   2048
#define HID   1024
#define NH    16
#define HD    64

// Scratch for Q, K, V in [b, h, s, d] layout (16 MB each). Static device
// globals — no allocation at runtime (allowed by harness rules).
__device__ float g_Q[BATCH * NH * SEQ * HD];
__device__ float g_K[BATCH * NH * SEQ * HD];
__device__ float g_V[BATCH * NH * SEQ * HD];

// ---------------------------------------------------------------------------
// QKV projection: out[m, n] = (sum_k X[m,k] * W[n,k] + bias[n]) * scale
// M = BATCH*SEQ = 4096, N = HID = 1024, K = HID = 1024.
// Tile 64x64, 256 threads, 4x4 per thread. Smem tiles stored k-major so the
// inner loop uses LDS.128 for both operands (FFMA-bound, not LDS-bound).
// Each N-tile (64 cols) is exactly one head -> blockIdx.x == head index.
// Output written to [b, h, s, d] scratch.
// ---------------------------------------------------------------------------
__global__ __launch_bounds__(256) void qkv_proj(
    const float* __restrict__ X,
    const float* __restrict__ Wq, const float* __restrict__ bq,
    const float* __restrict__ Wk,
    const float* __restrict__ Wv, const float* __restrict__ bv)
{
    const int sel = blockIdx.z;
    const float* __restrict__ W    = (sel == 0) ? Wq : ((sel == 1) ? Wk : Wv);
    const float* __restrict__ bias = (sel == 0) ? bq : ((sel == 1) ? nullptr : bv);
    float* __restrict__ out        = (sel == 0) ? g_Q : ((sel == 1) ? g_K : g_V);
    const float scale = (sel == 0) ? 0.125f : 1.0f;   // 1/sqrt(64) folded into Q

    __shared__ __align__(16) float Xs[16][68];  // [k][m]
    __shared__ __align__(16) float Ws[16][68];  // [k][n]

    const int tid = threadIdx.x;
    const int tx  = tid & 15;
    const int ty  = tid >> 4;
    const int m0  = blockIdx.y * 64;
    const int h   = blockIdx.x;       // head
    const int n0  = h * 64;

    const int lr = tid >> 2;          // 0..63: row within tile for loading
    const int lc = (tid & 3) * 4;     // 0,4,8,12: k offset

    float acc[4][4] = {};

    for (int k0 = 0; k0 < HID; k0 += 16) {
        float4 xv = *reinterpret_cast<const float4*>(&X[(size_t)(m0 + lr) * HID + k0 + lc]);
        float4 wv = *reinterpret_cast<const float4*>(&W[(size_t)(n0 + lr) * HID + k0 + lc]);
        Xs[lc + 0][lr] = xv.x; Xs[lc + 1][lr] = xv.y;
        Xs[lc + 2][lr] = xv.z; Xs[lc + 3][lr] = xv.w;
        Ws[lc + 0][lr] = wv.x; Ws[lc + 1][lr] = wv.y;
        Ws[lc + 2][lr] = wv.z; Ws[lc + 3][lr] = wv.w;
        __syncthreads();
        #pragma unroll
        for (int kk = 0; kk < 16; ++kk) {
            float4 a = *reinterpret_cast<const float4*>(&Xs[kk][ty * 4]);
            float4 b = *reinterpret_cast<const float4*>(&Ws[kk][tx * 4]);
            float av[4] = {a.x, a.y, a.z, a.w};
            float bvv[4] = {b.x, b.y, b.z, b.w};
            #pragma unroll
            for (int i = 0; i < 4; ++i)
                #pragma unroll
                for (int j = 0; j < 4; ++j)
                    acc[i][j] += av[i] * bvv[j];
        }
        __syncthreads();
    }

    float bias4[4] = {0.f, 0.f, 0.f, 0.f};
    if (bias) {
        #pragma unroll
        for (int j = 0; j < 4; ++j) bias4[j] = bias[n0 + tx * 4 + j];
    }

    #pragma unroll
    for (int i = 0; i < 4; ++i) {
        const int m    = m0 + ty * 4 + i;
        const int bidx = m >> 11;       // / SEQ
        const int s    = m & (SEQ - 1);
        float4 o;
        o.x = (acc[i][0] + bias4[0]) * scale;
        o.y = (acc[i][1] + bias4[1]) * scale;
        o.z = (acc[i][2] + bias4[2]) * scale;
        o.w = (acc[i][3] + bias4[3]) * scale;
        float* op = &out[(((size_t)bidx * NH + h) * SEQ + s) * HD + tx * 4];
        *reinterpret_cast<float4*>(op) = o;
    }
}

// ---------------------------------------------------------------------------
// Flash attention: per block = (q-tile of 64 rows, head, batch).
// Online softmax, never materializes the 2048x2048 score matrix.
// Smem: Qs [k][m] (k-major), KPs [k][n] for K then reused as P [kv][m],
// Vs [kv][d]. All inner-loop reads are LDS.128.
// ---------------------------------------------------------------------------
#define FLASH_STRIDE 68
#define FLASH_SMEM_FLOATS (3 * 64 * FLASH_STRIDE + 64)
#define FLASH_SMEM_BYTES  (FLASH_SMEM_FLOATS * 4)

__global__ __launch_bounds__(256) void flash_attn(
    const float* __restrict__ mask, float* __restrict__ out)
{
    extern __shared__ __align__(16) float sm[];
    float* Qs  = sm;                          // [64][68] : Q as [d][m]
    float* KPs = sm + 64 * FLASH_STRIDE;      // [64][68] : K as [d][n], then P as [kv][m]
    float* Vs  = sm + 2 * 64 * FLASH_STRIDE;  // [64][68] : V as [kv][d]
    float* mk  = sm + 3 * 64 * FLASH_STRIDE;  // [64] mask slice

    const int tid  = threadIdx.x;
    const int tx   = tid & 15;
    const int ty   = tid >> 4;
    const int q0   = blockIdx.x * 64;
    const int h    = blockIdx.y;
    const int bidx = blockIdx.z;
    const size_t base = ((size_t)bidx * NH + h) * SEQ * HD;

    // Load Q tile, transposed to [d][m]
    #pragma unroll
    for (int it = 0; it < 4; ++it) {
        int e = tid + it * 256;
        int r = e >> 4;            // q row 0..63
        int c = (e & 15) * 4;      // d offset
        float4 v = *reinterpret_cast<const float4*>(&g_Q[base + (size_t)(q0 + r) * HD + c]);
        Qs[(c + 0) * FLASH_STRIDE + r] = v.x;
        Qs[(c + 1) * FLASH_STRIDE + r] = v.y;
        Qs[(c + 2) * FLASH_STRIDE + r] = v.z;
        Qs[(c + 3) * FLASH_STRIDE + r] = v.w;
    }

    float ctx[4][4] = {};
    float mi[4] = {-INFINITY, -INFINITY, -INFINITY, -INFINITY};
    float li[4] = {};

    for (int kv0 = 0; kv0 < SEQ; kv0 += 64) {
        // Load K (transposed [d][n]) and V (natural [kv][d])
        #pragma unroll
        for (int it = 0; it < 4; ++it) {
            int e = tid + it * 256;
            int r = e >> 4;
            int c = (e & 15) * 4;
            float4 kv = *reinterpret_cast<const float4*>(&g_K[base + (size_t)(kv0 + r) * HD + c]);
            KPs[(c + 0) * FLASH_STRIDE + r] = kv.x;
            KPs[(c + 1) * FLASH_STRIDE + r] = kv.y;
            KPs[(c + 2) * FLASH_STRIDE + r] = kv.z;
            KPs[(c + 3) * FLASH_STRIDE + r] = kv.w;
            float4 vv = *reinterpret_cast<const float4*>(&g_V[base + (size_t)(kv0 + r) * HD + c]);
            *reinterpret_cast<float4*>(&Vs[r * FLASH_STRIDE + c]) = vv;
        }
        if (tid < 64) mk[tid] = mask[(size_t)bidx * SEQ + kv0 + tid];
        __syncthreads();

        // S = Q @ K^T (scale already folded into Q)
        float s_[4][4] = {};
        #pragma unroll 16
        for (int kk = 0; kk < 64; ++kk) {
            float4 a = *reinterpret_cast<const float4*>(&Qs[kk * FLASH_STRIDE + ty * 4]);
            float4 b = *reinterpret_cast<const float4*>(&KPs[kk * FLASH_STRIDE + tx * 4]);
            float av[4] = {a.x, a.y, a.z, a.w};
            float bv[4] = {b.x, b.y, b.z, b.w};
            #pragma unroll
            for (int i = 0; i < 4; ++i)
                #pragma unroll
                for (int j = 0; j < 4; ++j)
                    s_[i][j] += av[i] * bv[j];
        }

        // + attention_mask (broadcast over q rows and heads)
        float m4[4];
        #pragma unroll
        for (int j = 0; j < 4; ++j) m4[j] = mk[tx * 4 + j];
        #pragma unroll
        for (int i = 0; i < 4; ++i)
            #pragma unroll
            for (int j = 0; j < 4; ++j) s_[i][j] += m4[j];

        // Online softmax update (row reductions over 16 lanes sharing ty)
        #pragma unroll
        for (int i = 0; i < 4; ++i) {
            float mx = fmaxf(fmaxf(s_[i][0], s_[i][1]), fmaxf(s_[i][2], s_[i][3]));
            #pragma unroll
            for (int o = 1; o < 16; o <<= 1)
                mx = fmaxf(mx, __shfl_xor_sync(0xffffffffu, mx, o));
            float nm = fmaxf(mi[i], mx);
            float sum = 0.f;
            #pragma unroll
            for (int j = 0; j < 4; ++j) {
                s_[i][j] = __expf(s_[i][j] - nm);
                sum += s_[i][j];
            }
            #pragma unroll
            for (int o = 1; o < 16; o <<= 1)
                sum += __shfl_xor_sync(0xffffffffu, sum, o);
            float corr = __expf(mi[i] - nm);
            li[i] = li[i] * corr + sum;
            mi[i] = nm;
            #pragma unroll
            for (int j = 0; j < 4; ++j) ctx[i][j] *= corr;
        }

        __syncthreads();  // done reading K from KPs

        // Write P transposed: P[kv][m]
        #pragma unroll
        for (int i = 0; i < 4; ++i)
            #pragma unroll
            for (int j = 0; j < 4; ++j)
                KPs[(tx * 4 + j) * FLASH_STRIDE + (ty * 4 + i)] = s_[i][j];
        __syncthreads();

        // ctx += P @ V
        #pragma unroll 16
        for (int kk = 0; kk < 64; ++kk) {
            float4 a = *reinterpret_cast<const float4*>(&KPs[kk * FLASH_STRIDE + ty * 4]);
            float4 b = *reinterpret_cast<const float4*>(&Vs[kk * FLASH_STRIDE + tx * 4]);
            float av[4] = {a.x, a.y, a.z, a.w};
            float bv[4] = {b.x, b.y, b.z, b.w};
            #pragma unroll
            for (int i = 0; i < 4; ++i)
                #pragma unroll
                for (int j = 0; j < 4; ++j)
                    ctx[i][j] += av[i] * bv[j];
        }
        __syncthreads();  // before next tile load overwrites KPs/Vs
    }

    // Epilogue: normalize and write [b, s, h*64 + d]
    #pragma unroll
    for (int i = 0; i < 4; ++i) {
        const float inv = 1.0f / li[i];
        const int srow = q0 + ty * 4 + i;
        float4 o;
        o.x = ctx[i][0] * inv;
        o.y = ctx[i][1] * inv;
        o.z = ctx[i][2] * inv;
        o.w = ctx[i][3] * inv;
        float* op = &out[((size_t)bidx * SEQ + srow) * HID + h * HD + tx * 4];
        *reinterpret_cast<float4*>(op) = o;
    }
}

// ---------------------------------------------------------------------------
// Launch
// ---------------------------------------------------------------------------
extern "C" void kernel_launch(void* const* d_in, const int* in_sizes, int n_in,
                              void* d_out, int out_size)
{
    const float* hs   = (const float*)d_in[0];  // [2, 2048, 1024]
    const float* mask = (const float*)d_in[1];  // [2, 1, 1, 2048]
    const float* Wq   = (const float*)d_in[2];
    const float* bq   = (const float*)d_in[3];
    const float* Wk   = (const float*)d_in[4];
    const float* Wv   = (const float*)d_in[5];
    const float* bv   = (const float*)d_in[6];
    float* out = (float*)d_out;

    // QKV projection: grid (N-tiles=16 heads, M-tiles=64, qkv=3)
    dim3 gp(NH, (BATCH * SEQ) / 64, 3);
    qkv_proj<<<gp, 256>>>(hs, Wq, bq, Wk, Wv, bv);

    // Flash attention: grid (q-tiles=32, heads=16, batch=2)
    cudaFuncSetAttribute(flash_attn, cudaFuncAttributeMaxDynamicSharedMemorySize,
                         FLASH_SMEM_BYTES);
    dim3 ga(SEQ / 64, NH, BATCH);
    flash_attn<<<ga, 256, FLASH_SMEM_BYTES>>>(mask, out);
}

// round 3
// speedup vs baseline: 2.6382x; 2.6382x over previous
#include <cuda_runtime.h>
#include <cuda_bf16.h>
#include <math.h>
#include <stdint.h>

#define BATCH 2
#define SEQ   2048
#define HID   1024
#define NH    16
#define HD    64
#define LOG2E 1.4426950408889634f
#define SQSCALE (0.125f * LOG2E)   // 1/sqrt(64) * log2(e), folded into Q

// ---------------------------------------------------------------------------
// Device scratch (static globals; no runtime allocation)
// ---------------------------------------------------------------------------
__device__ __nv_bfloat16 g_Xhi[BATCH * SEQ * HID];
__device__ __nv_bfloat16 g_Xlo[BATCH * SEQ * HID];
__device__ __nv_bfloat16 g_Whi[3 * HID * HID];
__device__ __nv_bfloat16 g_Wlo[3 * HID * HID];
__device__ __nv_bfloat16 g_Qhi[BATCH * NH * SEQ * HD];  // [b,h,s,d]
__device__ __nv_bfloat16 g_Qlo[BATCH * NH * SEQ * HD];
__device__ __nv_bfloat16 g_Khi[BATCH * NH * SEQ * HD];  // [b,h,s,d]
__device__ __nv_bfloat16 g_Klo[BATCH * NH * SEQ * HD];
__device__ __nv_bfloat16 g_Vhi[BATCH * NH * HD * SEQ];  // [b,h,d,s] (transposed)
__device__ __nv_bfloat16 g_Vlo[BATCH * NH * HD * SEQ];

// ---------------------------------------------------------------------------
// Helpers
// ---------------------------------------------------------------------------
__device__ __forceinline__ uint32_t smem_to_u32(const void* p) {
    uint32_t a;
    asm("{ .reg .u64 t; cvta.to.shared.u64 t, %1; cvt.u32.u64 %0, t; }"
        : "=r"(a) : "l"(p));
    return a;
}

__device__ __forceinline__ void ldsm4(uint32_t* r, uint32_t addr) {
    asm volatile("ldmatrix.sync.aligned.m8n8.x4.shared.b16 {%0,%1,%2,%3}, [%4];"
        : "=r"(r[0]), "=r"(r[1]), "=r"(r[2]), "=r"(r[3]) : "r"(addr));
}

// D += A * B   (m16n8k16, bf16 in, fp32 accum)
__device__ __forceinline__ void mma16816(float* c, const uint32_t* a, const uint32_t* b) {
    asm volatile(
        "mma.sync.aligned.m16n8k16.row.col.f32.bf16.bf16.f32 "
        "{%0,%1,%2,%3}, {%4,%5,%6,%7}, {%8,%9}, {%0,%1,%2,%3};"
        : "+f"(c[0]), "+f"(c[1]), "+f"(c[2]), "+f"(c[3])
        : "r"(a[0]), "r"(a[1]), "r"(a[2]), "r"(a[3]), "r"(b[0]), "r"(b[1]));
}

// Fast exp2 on FMA/ALU pipes (no MUFU). x <= 0 expected; ~2.4e-6 rel err.
__device__ __forceinline__ float exp2_fast(float x) {
    x = fmaxf(x, -100.0f);
    float z  = x + 12582912.0f;                 // round to nearest int (1.5*2^23)
    float kf = z - 12582912.0f;
    float f  = x - kf;                          // [-0.5, 0.5]
    int   n  = __float_as_int(z) - 0x4B400000;  // = (int)kf
    float p  = 1.3333558146428443e-3f;
    p = fmaf(p, f, 9.6181291076284772e-3f);
    p = fmaf(p, f, 5.5504108664821580e-2f);
    p = fmaf(p, f, 2.4022650695910072e-1f);
    p = fmaf(p, f, 6.9314718055994531e-1f);
    p = fmaf(p, f, 1.0f);
    return p * __int_as_float((n + 127) << 23);
}

__device__ __forceinline__ uint32_t pack_hi2(float a, float b, float& la, float& lb) {
    __nv_bfloat16 h0 = __float2bfloat16_rn(a);
    __nv_bfloat16 h1 = __float2bfloat16_rn(b);
    la = a - __bfloat162float(h0);
    lb = b - __bfloat162float(h1);
    __nv_bfloat162 h = __halves2bfloat162(h0, h1);
    return *reinterpret_cast<uint32_t*>(&h);
}
__device__ __forceinline__ uint32_t pack_bf2(float a, float b) {
    __nv_bfloat162 h = __halves2bfloat162(__float2bfloat16_rn(a), __float2bfloat16_rn(b));
    return *reinterpret_cast<uint32_t*>(&h);
}

// ---------------------------------------------------------------------------
// Kernel 1: split fp32 -> (hi, lo) bf16
// ---------------------------------------------------------------------------
__global__ __launch_bounds__(256) void split_bf16(
    const float* __restrict__ X, const float* __restrict__ Wq,
    const float* __restrict__ Wk, const float* __restrict__ Wv)
{
    const int t = blockIdx.y;
    const float* src;
    __nv_bfloat16 *dhi, *dlo;
    int n4;
    if (t == 0) { src = X; dhi = g_Xhi; dlo = g_Xlo; n4 = (BATCH * SEQ * HID) / 4; }
    else {
        src = (t == 1) ? Wq : ((t == 2) ? Wk : Wv);
        dhi = g_Whi + (size_t)(t - 1) * HID * HID;
        dlo = g_Wlo + (size_t)(t - 1) * HID * HID;
        n4  = (HID * HID) / 4;
    }
    int i = blockIdx.x * 256 + threadIdx.x;
    if (i >= n4) return;
    float4 v = reinterpret_cast<const float4*>(src)[i];
    float l0, l1, l2, l3;
    uint32_t h01 = pack_hi2(v.x, v.y, l0, l1);
    uint32_t h23 = pack_hi2(v.z, v.w, l2, l3);
    reinterpret_cast<uint32_t*>(dhi)[i * 2 + 0] = h01;
    reinterpret_cast<uint32_t*>(dhi)[i * 2 + 1] = h23;
    reinterpret_cast<uint32_t*>(dlo)[i * 2 + 0] = pack_bf2(l0, l1);
    reinterpret_cast<uint32_t*>(dlo)[i * 2 + 1] = pack_bf2(l2, l3);
}

// ---------------------------------------------------------------------------
// Kernel 2: QKV projection via mma.sync bf16 3-term split.
// CTA tile 128m x 128n, K chunks of 64. 8 warps = 4(m) x 2(n), warp 32x64.
// ---------------------------------------------------------------------------
#define PJ_T   144                 // smem row pitch bytes (64 bf16 + 16B pad)
#define PJ_AHI 0
#define PJ_ALO 18432
#define PJ_BHI 36864
#define PJ_BLO 55296
#define PJ_BYTES 73728

__global__ __launch_bounds__(256) void qkv_proj(
    const float* __restrict__ bq, const float* __restrict__ bv)
{
    extern __shared__ char sm[];
    const uint32_t sb = smem_to_u32(sm);
    const int tid = threadIdx.x, lane = tid & 31, wid = tid >> 5;
    const int wm = wid & 3, wn = wid >> 2;
    const int sel = blockIdx.z;
    const int n0 = blockIdx.x * 128, m0 = blockIdx.y * 128;
    const __nv_bfloat16* __restrict__ Wh = g_Whi + (size_t)sel * HID * HID;
    const __nv_bfloat16* __restrict__ Wl = g_Wlo + (size_t)sel * HID * HID;

    const int a_row = (lane & 7) + ((lane >> 3) & 1) * 8;
    const int a_k   = (lane >> 4) * 8;
    const int b_row = (lane & 7) + ((lane >> 4) & 1) * 8;
    const int b_k   = ((lane >> 3) & 1) * 8;

    float acc[2][8][4] = {};

    for (int c = 0; c < 16; ++c) {
        const int k0 = c * 64;
        #pragma unroll
        for (int t = 0; t < 4; ++t) {
            int idx = tid + t * 256;
            int row = idx >> 3, c16 = idx & 7;
            size_t ga = (size_t)(m0 + row) * HID + k0 + c16 * 8;
            size_t gb = (size_t)(n0 + row) * HID + k0 + c16 * 8;
            uint32_t so = row * PJ_T + c16 * 16;
            *reinterpret_cast<uint4*>(sm + PJ_AHI + so) = *reinterpret_cast<const uint4*>(g_Xhi + ga);
            *reinterpret_cast<uint4*>(sm + PJ_ALO + so) = *reinterpret_cast<const uint4*>(g_Xlo + ga);
            *reinterpret_cast<uint4*>(sm + PJ_BHI + so) = *reinterpret_cast<const uint4*>(Wh + gb);
            *reinterpret_cast<uint4*>(sm + PJ_BLO + so) = *reinterpret_cast<const uint4*>(Wl + gb);
        }
        __syncthreads();
        #pragma unroll
        for (int kk = 0; kk < 4; ++kk) {
            uint32_t ah[2][4], al[2][4];
            #pragma unroll
            for (int mi = 0; mi < 2; ++mi) {
                uint32_t ra = sb + PJ_AHI + (wm * 32 + mi * 16 + a_row) * PJ_T
                            + (kk * 16 + a_k) * 2;
                ldsm4(ah[mi], ra);
                ldsm4(al[mi], ra + (PJ_ALO - PJ_AHI));
            }
            #pragma unroll
            for (int nj = 0; nj < 4; ++nj) {
                uint32_t bh[4], bl[4];
                uint32_t rb = sb + PJ_BHI + (wn * 64 + nj * 16 + b_row) * PJ_T
                            + (kk * 16 + b_k) * 2;
                ldsm4(bh, rb);
                ldsm4(bl, rb + (PJ_BLO - PJ_BHI));
                #pragma unroll
                for (int mi = 0; mi < 2; ++mi) {
                    mma16816(acc[mi][2 * nj],     ah[mi], bh);
                    mma16816(acc[mi][2 * nj + 1], ah[mi], bh + 2);
                    mma16816(acc[mi][2 * nj],     ah[mi], bl);
                    mma16816(acc[mi][2 * nj + 1], ah[mi], bl + 2);
                    mma16816(acc[mi][2 * nj],     al[mi], bh);
                    mma16816(acc[mi][2 * nj + 1], al[mi], bh + 2);
                }
            }
        }
        __syncthreads();
    }

    // Epilogue: bias/scale, split to bf16 hi/lo, store flash-ready layouts
    #pragma unroll
    for (int t8 = 0; t8 < 8; ++t8) {
        const int ng = n0 + wn * 64 + t8 * 8 + 2 * (lane & 3);
        const int h = ng >> 6, d = ng & 63;
        float2 bb = make_float2(0.f, 0.f);
        if (sel == 0) bb = *reinterpret_cast<const float2*>(bq + ng);
        if (sel == 2) bb = *reinterpret_cast<const float2*>(bv + ng);
        #pragma unroll
        for (int mi = 0; mi < 2; ++mi) {
            #pragma unroll
            for (int hf = 0; hf < 2; ++hf) {
                const int r = wm * 32 + mi * 16 + (lane >> 2) + hf * 8;
                const int m = m0 + r;
                const int b = m >> 11, s = m & (SEQ - 1);
                float v0 = acc[mi][t8][hf * 2 + 0] + bb.x;
                float v1 = acc[mi][t8][hf * 2 + 1] + bb.y;
                if (sel == 0) { v0 *= SQSCALE; v1 *= SQSCALE; }
                float l0, l1;
                uint32_t hp = pack_hi2(v0, v1, l0, l1);
                uint32_t lp = pack_bf2(l0, l1);
                if (sel == 2) {
                    size_t o = ((size_t)(b * NH + h) * HD + d) * SEQ + s;
                    __nv_bfloat162 h2 = *reinterpret_cast<__nv_bfloat162*>(&hp);
                    __nv_bfloat162 l2 = *reinterpret_cast<__nv_bfloat162*>(&lp);
                    g_Vhi[o] = __low2bfloat16(h2);  g_Vhi[o + SEQ] = __high2bfloat16(h2);
                    g_Vlo[o] = __low2bfloat16(l2);  g_Vlo[o + SEQ] = __high2bfloat16(l2);
                } else {
                    size_t o = ((size_t)(b * NH + h) * SEQ + s) * HD + d;
                    if (sel == 0) {
                        *reinterpret_cast<uint32_t*>(g_Qhi + o) = hp;
                        *reinterpret_cast<uint32_t*>(g_Qlo + o) = lp;
                    } else {
                        *reinterpret_cast<uint32_t*>(g_Khi + o) = hp;
                        *reinterpret_cast<uint32_t*>(g_Klo + o) = lp;
                    }
                }
            }
        }
    }
}

// ---------------------------------------------------------------------------
// Kernel 3: flash attention via mma.sync. BM=128, BN=128.
// 8 warps, each owns 16 q-rows (warp tile m16 x full width). P stays in regs.
// ---------------------------------------------------------------------------
#define FQK_T 144
#define FV_T  272
#define FQHI  0
#define FQLO  18432
#define FKHI  36864
#define FKLO  55296
#define FVHI  73728
#define FVLO  91136
#define FMK   108544
#define FA_BYTES 109056

__global__ __launch_bounds__(256) void flash(
    const float* __restrict__ mask, float* __restrict__ out)
{
    extern __shared__ char sm[];
    const uint32_t sb = smem_to_u32(sm);
    float* mk = reinterpret_cast<float*>(sm + FMK);
    const int tid = threadIdx.x, lane = tid & 31, wid = tid >> 5;
    const int q0 = blockIdx.x * 128, h = blockIdx.y, b = blockIdx.z;
    const size_t bh = (size_t)b * NH + h;

    const int a_row = (lane & 7) + ((lane >> 3) & 1) * 8;
    const int a_k   = (lane >> 4) * 8;
    const int b_row = (lane & 7) + ((lane >> 4) & 1) * 8;
    const int b_k   = ((lane >> 3) & 1) * 8;

    // Load Q tile (128 x 64 bf16, hi/lo)
    #pragma unroll
    for (int t = 0; t < 4; ++t) {
        int idx = tid + t * 256;
        int row = idx >> 3, c16 = idx & 7;
        size_t g = (bh * SEQ + q0 + row) * HD + c16 * 8;
        uint32_t so = row * FQK_T + c16 * 16;
        *reinterpret_cast<uint4*>(sm + FQHI + so) = *reinterpret_cast<const uint4*>(g_Qhi + g);
        *reinterpret_cast<uint4*>(sm + FQLO + so) = *reinterpret_cast<const uint4*>(g_Qlo + g);
    }
    __syncthreads();

    // Q fragments held in registers for the whole kernel
    uint32_t qh[4][4], ql[4][4];
    #pragma unroll
    for (int kk = 0; kk < 4; ++kk) {
        uint32_t ra = sb + FQHI + (wid * 16 + a_row) * FQK_T + (kk * 16 + a_k) * 2;
        ldsm4(qh[kk], ra);
        ldsm4(ql[kk], ra + (FQLO - FQHI));
    }

    float ctx[8][4] = {};
    float miA = -1e30f, miB = -1e30f, liA = 0.f, liB = 0.f;

    for (int kv0 = 0; kv0 < SEQ; kv0 += 128) {
        #pragma unroll
        for (int t = 0; t < 4; ++t) {
            int idx = tid + t * 256;
            {   int row = idx >> 3, c16 = idx & 7;
                size_t g = (bh * SEQ + kv0 + row) * HD + c16 * 8;
                uint32_t so = row * FQK_T + c16 * 16;
                *reinterpret_cast<uint4*>(sm + FKHI + so) = *reinterpret_cast<const uint4*>(g_Khi + g);
                *reinterpret_cast<uint4*>(sm + FKLO + so) = *reinterpret_cast<const uint4*>(g_Klo + g); }
            {   int row = idx >> 4, c16 = idx & 15;
                size_t g = (bh * HD + row) * SEQ + kv0 + c16 * 8;
                uint32_t so = row * FV_T + c16 * 16;
                *reinterpret_cast<uint4*>(sm + FVHI + so) = *reinterpret_cast<const uint4*>(g_Vhi + g);
                *reinterpret_cast<uint4*>(sm + FVLO + so) = *reinterpret_cast<const uint4*>(g_Vlo + g); }
        }
        if (tid < 128) mk[tid] = mask[(size_t)b * SEQ + kv0 + tid] * LOG2E;
        __syncthreads();

        // ---- S = Q K^T (3-term split), log2-domain scores ----
        float s[16][4] = {};
        #pragma unroll
        for (int kk = 0; kk < 4; ++kk) {
            #pragma unroll
            for (int nj = 0; nj < 8; ++nj) {
                uint32_t kh[4], kl[4];
                uint32_t rb = sb + FKHI + (nj * 16 + b_row) * FQK_T + (kk * 16 + b_k) * 2;
                ldsm4(kh, rb);
                ldsm4(kl, rb + (FKLO - FKHI));
                mma16816(s[2 * nj],     qh[kk], kh);
                mma16816(s[2 * nj + 1], qh[kk], kh + 2);
                mma16816(s[2 * nj],     qh[kk], kl);
                mma16816(s[2 * nj + 1], qh[kk], kl + 2);
                mma16816(s[2 * nj],     ql[kk], kh);
                mma16816(s[2 * nj + 1], ql[kk], kh + 2);
            }
        }

        // ---- mask + online softmax (rows owned by one quad) ----
        float mxA = -1e30f, mxB = -1e30f;
        #pragma unroll
        for (int t = 0; t < 16; ++t) {
            float2 mv = *reinterpret_cast<const float2*>(mk + t * 8 + 2 * (lane & 3));
            s[t][0] += mv.x; s[t][1] += mv.y;
            s[t][2] += mv.x; s[t][3] += mv.y;
            mxA = fmaxf(mxA, fmaxf(s[t][0], s[t][1]));
            mxB = fmaxf(mxB, fmaxf(s[t][2], s[t][3]));
        }
        mxA = fmaxf(mxA, __shfl_xor_sync(0xffffffffu, mxA, 1));
        mxA = fmaxf(mxA, __shfl_xor_sync(0xffffffffu, mxA, 2));
        mxB = fmaxf(mxB, __shfl_xor_sync(0xffffffffu, mxB, 1));
        mxB = fmaxf(mxB, __shfl_xor_sync(0xffffffffu, mxB, 2));
        float nmA = fmaxf(miA, mxA), nmB = fmaxf(miB, mxB);
        float corrA = exp2_fast(miA - nmA), corrB = exp2_fast(miB - nmB);
        miA = nmA; miB = nmB;
        float sA = 0.f, sB = 0.f;
        #pragma unroll
        for (int t = 0; t < 16; ++t) {
            s[t][0] = exp2_fast(s[t][0] - nmA);
            s[t][1] = exp2_fast(s[t][1] - nmA);
            s[t][2] = exp2_fast(s[t][2] - nmB);
            s[t][3] = exp2_fast(s[t][3] - nmB);
            sA += s[t][0] + s[t][1];
            sB += s[t][2] + s[t][3];
        }
        sA += __shfl_xor_sync(0xffffffffu, sA, 1);
        sA += __shfl_xor_sync(0xffffffffu, sA, 2);
        sB += __shfl_xor_sync(0xffffffffu, sB, 1);
        sB += __shfl_xor_sync(0xffffffffu, sB, 2);
        liA = liA * corrA + sA;
        liB = liB * corrB + sB;
        #pragma unroll
        for (int t = 0; t < 8; ++t) {
            ctx[t][0] *= corrA; ctx[t][1] *= corrA;
            ctx[t][2] *= corrB; ctx[t][3] *= corrB;
        }

        // ---- ctx += P V : P fragments built in registers from s ----
        #pragma unroll
        for (int j = 0; j < 8; ++j) {
            uint32_t ph[4], pl[4];
            #pragma unroll
            for (int u = 0; u < 2; ++u) {
                float l0, l1, l2, l3;
                ph[2 * u + 0] = pack_hi2(s[2 * j + u][0], s[2 * j + u][1], l0, l1);
                ph[2 * u + 1] = pack_hi2(s[2 * j + u][2], s[2 * j + u][3], l2, l3);
                pl[2 * u + 0] = pack_bf2(l0, l1);
                pl[2 * u + 1] = pack_bf2(l2, l3);
            }
            #pragma unroll
            for (int dn = 0; dn < 4; ++dn) {
                uint32_t vh[4], vl[4];
                uint32_t rb = sb + FVHI + (dn * 16 + b_row) * FV_T + (j * 16 + b_k) * 2;
                ldsm4(vh, rb);
                ldsm4(vl, rb + (FVLO - FVHI));
                mma16816(ctx[2 * dn],     ph, vh);
                mma16816(ctx[2 * dn + 1], ph, vh + 2);
                mma16816(ctx[2 * dn],     ph, vl);
                mma16816(ctx[2 * dn + 1], ph, vl + 2);
                mma16816(ctx[2 * dn],     pl, vh);
                mma16816(ctx[2 * dn + 1], pl, vh + 2);
            }
        }
        __syncthreads();  // before next iteration overwrites K/V/mk
    }

    // Epilogue: normalize, store [b, s, h*64+d]
    const float invA = 1.0f / liA, invB = 1.0f / liB;
    const int rA = q0 + wid * 16 + (lane >> 2);
    #pragma unroll
    for (int t = 0; t < 8; ++t) {
        const int col = h * HD + t * 8 + 2 * (lane & 3);
        float2 oA = make_float2(ctx[t][0] * invA, ctx[t][1] * invA);
        float2 oB = make_float2(ctx[t][2] * invB, ctx[t][3] * invB);
        *reinterpret_cast<float2*>(out + ((size_t)b * SEQ + rA) * HID + col)     = oA;
        *reinterpret_cast<float2*>(out + ((size_t)b * SEQ + rA + 8) * HID + col) = oB;
    }
}

// ---------------------------------------------------------------------------
// Launch
// ---------------------------------------------------------------------------
extern "C" void kernel_launch(void* const* d_in, const int* in_sizes, int n_in,
                              void* d_out, int out_size)
{
    const float* hs   = (const float*)d_in[0];
    const float* mask = (const float*)d_in[1];
    const float* Wq   = (const float*)d_in[2];
    const float* bq   = (const float*)d_in[3];
    const float* Wk   = (const float*)d_in[4];
    const float* Wv   = (const float*)d_in[5];
    const float* bv   = (const float*)d_in[6];
    float* out = (float*)d_out;

    dim3 gs((BATCH * SEQ * HID / 4 + 255) / 256, 4);
    split_bf16<<<gs, 256>>>(hs, Wq, Wk, Wv);

    cudaFuncSetAttribute(qkv_proj, cudaFuncAttributeMaxDynamicSharedMemorySize, PJ_BYTES);
    qkv_proj<<<dim3(8, 32, 3), 256, PJ_BYTES>>>(bq, bv);

    cudaFuncSetAttribute(flash, cudaFuncAttributeMaxDynamicSharedMemorySize, FA_BYTES);
    flash<<<dim3(SEQ / 128, NH, BATCH), 256, FA_BYTES>>>(mask, out);
}